// round 6
// baseline (speedup 1.0000x reference)
#include <cuda_runtime.h>
#include <cuda_bf16.h>
#include <math.h>

#define C_DIM    40
#define VPR      10                   // float4 vectors per row (data)
#define VPAD     11                   // padded vectors per row -> 44 floats, conflict-free LDS.128
#define THREADS  256
#define WARPS    (THREADS / 32)
#define ROWS_PER_WARP 32
#define ROWS     (WARPS * ROWS_PER_WARP)   // 256 rows per block

__global__ void init_out_kernel(float* out) {
    out[0] = 0.0f;
}

__global__ __launch_bounds__(THREADS) void hier_loss_kernel(
    const float* __restrict__ logits,   // [B, 40]
    const int*   __restrict__ labels,   // [B]
    const float* __restrict__ dis,      // [40, 40]
    float* __restrict__ out,            // out[0]=loss, out[1..B]=distance_factor
    int B)
{
    __shared__ float4 s4[ROWS * VPAD];  // 256*11*16 = 45056 B
    __shared__ float  wsum[WARPS];

    const int tid  = threadIdx.x;
    const int lane = tid & 31;
    const int warp = tid >> 5;

    const int warpRow = blockIdx.x * ROWS + warp * ROWS_PER_WARP;   // first row of this warp's tile

    // ---- warp-private staging: 32 rows = 320 float4, fully coalesced ----
    float4* slice = s4 + warp * ROWS_PER_WARP * VPAD;
    {
        const float4* src = reinterpret_cast<const float4*>(logits + (long long)warpRow * C_DIM);
        #pragma unroll
        for (int j = 0; j < VPR; j++) {                 // 10 iterations, 128B/warp each
            int i = lane + 32 * j;                      // 0..319
            float4 q = __ldg(src + i);
            int r = i / VPR;                            // const-div -> mul/shift
            int c = i - r * VPR;
            slice[r * VPAD + c] = q;
        }
    }
    __syncwarp();

    // ---- each thread consumes one row from its warp's slice via 10x LDS.128 ----
    float contrib = 0.0f;
    const int row = warpRow + lane;
    if (row < B) {
        const float4* rowp = slice + lane * VPAD;

        float v[C_DIM];
        #pragma unroll
        for (int k = 0; k < VPR; k++) {
            float4 q = rowp[k];
            v[4 * k + 0] = q.x;
            v[4 * k + 1] = q.y;
            v[4 * k + 2] = q.z;
            v[4 * k + 3] = q.w;
        }

        // max + argmax (first occurrence)
        float mx = v[0];
        int   am = 0;
        #pragma unroll
        for (int i = 1; i < C_DIM; i++) {
            if (v[i] > mx) { mx = v[i]; am = i; }
        }

        // sum exp(x - max)
        float ssum = 0.0f;
        #pragma unroll
        for (int i = 0; i < C_DIM; i++) {
            ssum += __expf(v[i] - mx);
        }

        int lbl = __ldg(labels + row);
        // x[label] via scalar LDS (avoids dynamic register indexing / spills)
        float xl = reinterpret_cast<const float*>(rowp)[lbl];

        float ce = __logf(ssum) + mx - xl;
        float df = __ldg(dis + lbl * C_DIM + am) + 0.5f;
        out[1 + row] = df;
        contrib = ce * df;
    }

    // ---- warp-level sum, then cross-warp reduction ----
    #pragma unroll
    for (int off = 16; off > 0; off >>= 1)
        contrib += __shfl_xor_sync(0xFFFFFFFFu, contrib, off);

    if (lane == 0) wsum[warp] = contrib;
    __syncthreads();

    if (warp == 0) {
        float t = (lane < WARPS) ? wsum[lane] : 0.0f;
        #pragma unroll
        for (int off = 4; off > 0; off >>= 1)
            t += __shfl_xor_sync(0xFFFFFFFFu, t, off);
        if (lane == 0)
            atomicAdd(out, t * (1.0f / (float)B));
    }
}

extern "C" void kernel_launch(void* const* d_in, const int* in_sizes, int n_in,
                              void* d_out, int out_size) {
    const float* logits = (const float*)d_in[0];
    const int*   labels = (const int*)d_in[1];
    const float* dis    = (const float*)d_in[2];
    float* out = (float*)d_out;

    int B = in_sizes[1];

    init_out_kernel<<<1, 1>>>(out);

    int blocks = (B + ROWS - 1) / ROWS;
    hier_loss_kernel<<<blocks, THREADS>>>(logits, labels, dis, out, B);
}